// round 15
// baseline (speedup 1.0000x reference)
#include <cuda_runtime.h>
#include <cstdint>

// LossGenerator: T=11, H=W=2048. Inputs u=output, f1, each [11,1,2048,2048] f32.
// Output: [phy, bc] f32. Single fused kernel.
// R14 skeleton (best 80.6us): cp.async 4-slot pipeline, single barrier per t
// (wait_group -> syncthreads -> issue t+3), 5 CTAs/SM.
// R15 delta: f1 bypasses smem entirely -- direct LDG.64 with DISTANCE-2
// register prefetch (f(t+2) loaded at top of iteration t), removing the
// f-staging L1 charges (LDG-wf + smem-write + LDS-read ~= 24% of L1 cycles).

#define HH 2048
#define WI 2048
static const size_t HWs = (size_t)HH * (size_t)WI;

#define NB_BC   10
#define NB_PHY  8192     // 32 col-segments (64 px) x 256 row-groups (8 rows)
#define NB_TOT  (NB_BC + NB_PHY)

#define RS      68       // smem row stride (floats): 64 main + 2 halo + 2 pad
#define SU_ROW  10
#define SU_ST   (SU_ROW * RS)   // 680

__device__ double   g_phy;
__device__ double   g_bc;
__device__ unsigned g_count;

constexpr double PREFD = 3.5682482323055424;  // 0.1^{-0.5}/Gamma(1.5)
constexpr double WQ[10] = {
    1.0,
    0.41421356237309515,
    0.31783724519578215,
    0.26794919243112270,
    0.23606797749978969,
    0.21342176528338802,
    0.19626156828141264,
    0.18267581368159972,
    0.17157287525380971,
    0.16227766016837933
};

__device__ __forceinline__ void cp16(uint32_t s, const void* g) {
    asm volatile("cp.async.ca.shared.global [%0], [%1], 16;" :: "r"(s), "l"(g));
}
__device__ __forceinline__ void cp4(uint32_t s, const void* g) {
    asm volatile("cp.async.ca.shared.global [%0], [%1], 4;" :: "r"(s), "l"(g));
}
#define CP_COMMIT() asm volatile("cp.async.commit_group;" ::: "memory")
#define CP_WAIT2()  asm volatile("cp.async.wait_group 2;" ::: "memory")

__device__ __forceinline__ void block_reduce_add(double v, double* target, int tid) {
    #pragma unroll
    for (int o = 16; o > 0; o >>= 1)
        v += __shfl_down_sync(0xffffffffu, v, o);
    __shared__ double sr[8];
    int lane = tid & 31, wid = tid >> 5;
    if (lane == 0) sr[wid] = v;
    __syncthreads();
    if (wid == 0) {
        v = (lane < 8) ? sr[lane] : 0.0;
        #pragma unroll
        for (int o = 4; o > 0; o >>= 1)
            v += __shfl_down_sync(0xffffffffu, v, o);
        if (lane == 0) atomicAdd(target, v);
    }
}

__global__ __launch_bounds__(256, 5) void fused_kernel(const float* __restrict__ u,
                                                       const float* __restrict__ f1,
                                                       float* __restrict__ out) {
    const int tid = threadIdx.x;
    const int bid = blockIdx.x;

    __shared__ float su[4 * SU_ST];   // 10880 B

    if (bid < NB_BC) {
        // ---------------- boundary-condition loss ----------------
        const int it = bid;                      // time slice it+1
        const float* ut = u + (size_t)(it + 1) * HWs;
        const float tval = 0.1f + 0.1f * (float)it;
        const float tt = powf(tval, 1.5f);

        double v = 0.0;
        #pragma unroll
        for (int jb = 0; jb < 8; jb++) {
            const int j = jb * 256 + tid;        // 0..2047
            const float xj = (float)j * (1.0f / 2047.0f);
            const float x1b = tt * sinf(6.2831853071795862f * xj);

            const float l  = ut[(size_t)j * WI];
            const float r  = ut[(size_t)j * WI + (WI - 1)];
            const float tp = ut[j];
            const float bt = ut[(size_t)(HH - 1) * WI + j];

            const float dl = l - x1b, dr = r - x1b, du = tp - x1b, db = bt - x1b;
            v += (double)(dl * dl + dr * dr + du * du + db * db);
        }
        block_reduce_add(v, &g_bc, tid);
    } else {
        // ---------------- physics residual loss ----------------
        const int b     = bid - NB_BC;
        const int lane  = tid & 31;
        const int wrp   = tid >> 5;                 // 0..7 -> output row
        const int seg   = b & 31;                   // 64-px column strip
        const int hgrp  = b >> 5;                   // 0..255
        const int h0    = 1 + hgrp * 8;             // first output row
        const int wbase = seg * 64;
        const int h     = h0 + wrp;                 // this warp's output row
        const int w0    = wbase + lane * 2;         // first of 2 pixels

        const uint32_t su_base = (uint32_t)__cvta_generic_to_shared(su);

        // ---- loader assignment (fixed across t) ----
        // u tile: 10 rows x 16 chunks = 160 cp16 items -> tids 0..159.
        // halo:   10 rows x 2 sides   =  20 cp4  items -> tids 0..19.
        const bool ldu = (tid < 160);
        size_t gu_off = 0; uint32_t su_off = 0;
        if (ldu) {
            const int ur = tid >> 4, c = tid & 15;
            int hr = h0 - 1 + ur; if (hr > HH - 1) hr = HH - 1;
            gu_off = (size_t)hr * WI + wbase + 4 * c;
            su_off = su_base + (uint32_t)((ur * RS + 4 * c) * 4);
        }
        const bool ldh = (tid < 20);
        size_t gh_off = 0; uint32_t sh_off = 0;
        if (ldh) {
            const int hrr = tid >> 1, hside = tid & 1;
            int hr = h0 - 1 + hrr; if (hr > HH - 1) hr = HH - 1;
            int col = hside ? (wbase + 64 > WI - 1 ? WI - 1 : wbase + 64)
                            : (wbase - 1 < 0 ? 0 : wbase - 1);
            gh_off = (size_t)hr * WI + col;
            sh_off = su_base + (uint32_t)((hrr * RS + 64 + hside) * 4);
        }

        #define LOAD_STAGE(T, ST)                                                   \
        do {                                                                        \
            if (ldu)                                                                \
                cp16(su_off + (uint32_t)((ST) * SU_ST * 4),                         \
                     u + (size_t)(T) * HWs + gu_off);                               \
            if (ldh)                                                                \
                cp4(sh_off + (uint32_t)((ST) * SU_ST * 4),                          \
                    u + (size_t)(T) * HWs + gh_off);                                \
            CP_COMMIT();                                                            \
        } while (0)

        LOAD_STAGE(0, 0);
        LOAD_STAGE(1, 1);
        LOAD_STAGE(2, 2);

        const float A = 0.34520446044393f;
        const float B = 0.309591078922457f;
        const float C = -2.619182157203629f;
        const float KLAP = 0.01f * 4194304.0f;     // kappa / DX^2

        const float fPW[10] = {
            (float)(PREFD * WQ[0]), (float)(PREFD * WQ[1]), (float)(PREFD * WQ[2]),
            (float)(PREFD * WQ[3]), (float)(PREFD * WQ[4]), (float)(PREFD * WQ[5]),
            (float)(PREFD * WQ[6]), (float)(PREFD * WQ[7]), (float)(PREFD * WQ[8]),
            (float)(PREFD * WQ[9])
        };
        const float fPD[10] = {
            0.0f,
            (float)(PREFD * (WQ[0] - WQ[1])), (float)(PREFD * (WQ[1] - WQ[2])),
            (float)(PREFD * (WQ[2] - WQ[3])), (float)(PREFD * (WQ[3] - WQ[4])),
            (float)(PREFD * (WQ[4] - WQ[5])), (float)(PREFD * (WQ[5] - WQ[6])),
            (float)(PREFD * (WQ[6] - WQ[7])), (float)(PREFD * (WQ[7] - WQ[8])),
            (float)(PREFD * (WQ[8] - WQ[9]))
        };
        const float PREFF = (float)PREFD;

        const float mskA = (h <= HH - 2) ? 1.0f : 0.0f;
        const float msk0 = mskA * ((w0 == 0)      ? 0.0f : 1.0f);
        const float msk1 = mskA * ((w0 == WI - 2) ? 0.0f : 1.0f);

        // f1: direct LDG with distance-2 register prefetch.
        const int hf = (h > HH - 1) ? HH - 1 : h;
        const float* fp = f1 + (size_t)hf * WI + (size_t)w0;
        float2 fb0 = *(const float2*)fp;                 // slice 0
        float2 fb1 = *(const float2*)(fp + HWs);         // slice 1

        float acc = 0.0f;
        float ucm[11][2];

        #pragma unroll
        for (int t = 0; t < 11; t++) {
            const int st = t & 3;

            // Wait for own slice-t copies, then one barrier (collective
            // visibility + slot (t+3)&3 == (t-1)&3 free), then refill.
            CP_WAIT2();
            __syncthreads();
            if (t + 3 <= 10) { LOAD_STAGE(t + 3, (t + 3) & 3); }
            else             { CP_COMMIT(); }

            // f prefetch, distance 2: needed at iteration t+2.
            float2 fnew;
            if (t + 2 <= 10) fnew = *(const float2*)(fp + (size_t)(t + 2) * HWs);
            else             fnew = make_float2(0.f, 0.f);

            const float* rowT = su + st * SU_ST + wrp * RS;   // u row h-1
            const float* rowM = rowT + RS;                    // u row h
            const float* rowB = rowM + RS;                    // u row h+1

            const float2 a2 = *(const float2*)(rowT + 2 * lane);
            const float2 m2 = *(const float2*)(rowM + 2 * lane);
            const float2 b2 = *(const float2*)(rowB + 2 * lane);

            float qE = 0.0f;
            if (lane == 0 || lane == 31) {
                const int hi = (lane == 0) ? 64 : 65;
                qE = fmaf(A, rowT[hi] + rowB[hi], B * rowM[hi]);
            }

            const float ca0 = a2.x + b2.x, ca1 = a2.y + b2.y;
            const float q0 = fmaf(A, ca0, B * m2.x);
            const float q1 = fmaf(A, ca1, B * m2.y);

            float qL = __shfl_up_sync(0xffffffffu, q1, 1);
            float qR = __shfl_down_sync(0xffffffffu, q0, 1);
            if (lane == 0)  qL = qE;
            if (lane == 31) qR = qE;

            const float qa[4] = { qL, q0, q1, qR };
            const float ca[2] = { ca0, ca1 };
            const float mc[2] = { m2.x, m2.y };
            const float ff[2] = { fb0.x, fb0.y };
            const float msk[2] = { msk0, msk1 };

            #pragma unroll
            for (int j = 0; j < 2; j++) {
                const float center = mc[j];
                const float conv = qa[j] + qa[j + 2]
                                 + fmaf(B, ca[j], C * center);
                float fu = center - ff[j] - KLAP * conv;
                if (t > 0) {
                    float Dv = PREFF * center - fPW[t - 1] * ucm[0][j];
                    #pragma unroll
                    for (int k = 1; k < t; k++)
                        Dv -= fPD[t - k] * ucm[k][j];
                    fu += Dv;
                }
                fu *= msk[j];
                acc = fmaf(fu, fu, acc);
                ucm[t][j] = center;
            }

            fb0 = fb1;
            fb1 = fnew;
        }

        block_reduce_add((double)acc, &g_phy, tid);
        #undef LOAD_STAGE
    }

    // ---------------- last-block finalize + reset ----------------
    if (tid == 0) {
        __threadfence();
        unsigned prev = atomicAdd(&g_count, 1u);
        if (prev == NB_TOT - 1) {
            out[0] = (float)(2.0 * g_phy / 46047276.0);   // 11*2046*2046
            out[1] = (float)(g_bc / 41943040.0);          // 10*2048*2048
            g_phy = 0.0;
            g_bc  = 0.0;
            g_count = 0u;
            __threadfence();
        }
    }
}

extern "C" void kernel_launch(void* const* d_in, const int* in_sizes, int n_in,
                              void* d_out, int out_size) {
    const float* u  = (const float*)d_in[0];
    const float* f1 = (const float*)d_in[1];
    float* out = (float*)d_out;

    fused_kernel<<<NB_TOT, 256>>>(u, f1, out);
}

// round 16
// speedup vs baseline: 1.0666x; 1.0666x over previous
#include <cuda_runtime.h>
#include <cstdint>

// LossGenerator: T=11, H=W=2048. Inputs u=output, f1, each [11,1,2048,2048] f32.
// Output: [phy, bc] f32. Single fused kernel.
// R14 skeleton (best 80.6us): cp.async 4-slot pipeline staging u (10 rows +
// halo) AND f1 (8 rows); single barrier per t; 5 CTAs/SM.
// R16 delta: vertical-pair warps. Warp = 32 px x 2 output rows (1 px/thread,
// 2 warps horizontal x 4 vertical over the same 64x8 tile). 4 u-row reads per
// 2 output rows cuts u LDS bytes 33% (3->2 rows/output). History stays
// ucm[11][2] = 22 regs.

#define HH 2048
#define WI 2048
static const size_t HWs = (size_t)HH * (size_t)WI;

#define NB_BC   10
#define NB_PHY  8192     // 32 col-segments (64 px) x 256 row-groups (8 rows)
#define NB_TOT  (NB_BC + NB_PHY)

#define RS      68       // smem row stride (floats): 64 main + 2 halo + 2 pad
#define SU_ROW  10
#define SF_ROW  8
#define SU_ST   (SU_ROW * RS)   // 680
#define SF_ST   (SF_ROW * RS)   // 544

__device__ double   g_phy;
__device__ double   g_bc;
__device__ unsigned g_count;

constexpr double PREFD = 3.5682482323055424;  // 0.1^{-0.5}/Gamma(1.5)
constexpr double WQ[10] = {
    1.0,
    0.41421356237309515,
    0.31783724519578215,
    0.26794919243112270,
    0.23606797749978969,
    0.21342176528338802,
    0.19626156828141264,
    0.18267581368159972,
    0.17157287525380971,
    0.16227766016837933
};

__device__ __forceinline__ void cp16(uint32_t s, const void* g) {
    asm volatile("cp.async.ca.shared.global [%0], [%1], 16;" :: "r"(s), "l"(g));
}
__device__ __forceinline__ void cp4(uint32_t s, const void* g) {
    asm volatile("cp.async.ca.shared.global [%0], [%1], 4;" :: "r"(s), "l"(g));
}
#define CP_COMMIT() asm volatile("cp.async.commit_group;" ::: "memory")
#define CP_WAIT2()  asm volatile("cp.async.wait_group 2;" ::: "memory")

__device__ __forceinline__ void block_reduce_add(double v, double* target, int tid) {
    #pragma unroll
    for (int o = 16; o > 0; o >>= 1)
        v += __shfl_down_sync(0xffffffffu, v, o);
    __shared__ double sr[8];
    int lane = tid & 31, wid = tid >> 5;
    if (lane == 0) sr[wid] = v;
    __syncthreads();
    if (wid == 0) {
        v = (lane < 8) ? sr[lane] : 0.0;
        #pragma unroll
        for (int o = 4; o > 0; o >>= 1)
            v += __shfl_down_sync(0xffffffffu, v, o);
        if (lane == 0) atomicAdd(target, v);
    }
}

__global__ __launch_bounds__(256, 5) void fused_kernel(const float* __restrict__ u,
                                                       const float* __restrict__ f1,
                                                       float* __restrict__ out) {
    const int tid = threadIdx.x;
    const int bid = blockIdx.x;

    __shared__ float su[4 * SU_ST];   // 10880 B
    __shared__ float sf[4 * SF_ST];   //  8704 B

    if (bid < NB_BC) {
        // ---------------- boundary-condition loss ----------------
        const int it = bid;                      // time slice it+1
        const float* ut = u + (size_t)(it + 1) * HWs;
        const float tval = 0.1f + 0.1f * (float)it;
        const float tt = powf(tval, 1.5f);

        double v = 0.0;
        #pragma unroll
        for (int jb = 0; jb < 8; jb++) {
            const int j = jb * 256 + tid;        // 0..2047
            const float xj = (float)j * (1.0f / 2047.0f);
            const float x1b = tt * sinf(6.2831853071795862f * xj);

            const float l  = ut[(size_t)j * WI];
            const float r  = ut[(size_t)j * WI + (WI - 1)];
            const float tp = ut[j];
            const float bt = ut[(size_t)(HH - 1) * WI + j];

            const float dl = l - x1b, dr = r - x1b, du = tp - x1b, db = bt - x1b;
            v += (double)(dl * dl + dr * dr + du * du + db * db);
        }
        block_reduce_add(v, &g_bc, tid);
    } else {
        // ---------------- physics residual loss ----------------
        const int b     = bid - NB_BC;
        const int lane  = tid & 31;
        const int wrp   = tid >> 5;                 // 0..7
        const int seg   = b & 31;                   // 64-px column strip
        const int hgrp  = b >> 5;                   // 0..255
        const int h0    = 1 + hgrp * 8;             // first output row
        const int wbase = seg * 64;

        // Vertical-pair warp layout: wx = horizontal half, wy = row pair.
        const int wx = wrp & 1;                     // 0..1
        const int wy = wrp >> 1;                    // 0..3
        const int c  = wx * 32 + lane;              // tile col 0..63
        const int w  = wbase + c;                   // global col
        const int hA = h0 + 2 * wy;                 // output row A
        // output row B = hA + 1

        const uint32_t su_base = (uint32_t)__cvta_generic_to_shared(su);
        const uint32_t sf_base = (uint32_t)__cvta_generic_to_shared(sf);

        // ---- loader assignment (identical to R14) ----
        const bool ldu = (tid < 160);
        size_t gu_off = 0; uint32_t su_off = 0;
        if (ldu) {
            const int ur = tid >> 4, cc = tid & 15;
            int hr = h0 - 1 + ur; if (hr > HH - 1) hr = HH - 1;
            gu_off = (size_t)hr * WI + wbase + 4 * cc;
            su_off = su_base + (uint32_t)((ur * RS + 4 * cc) * 4);
        }
        const int  fitem = (tid >= 160) ? (tid - 160) : (tid < 32 ? 96 + tid : -1);
        const bool ldf = (fitem >= 0);
        size_t gf_off = 0; uint32_t sf_off = 0;
        if (ldf) {
            const int fr = fitem >> 4, cc = fitem & 15;
            int hr = h0 + fr; if (hr > HH - 1) hr = HH - 1;
            gf_off = (size_t)hr * WI + wbase + 4 * cc;
            sf_off = sf_base + (uint32_t)((fr * RS + 4 * cc) * 4);
        }
        const bool ldh = (tid < 20);
        size_t gh_off = 0; uint32_t sh_off = 0;
        if (ldh) {
            const int hrr = tid >> 1, hside = tid & 1;
            int hr = h0 - 1 + hrr; if (hr > HH - 1) hr = HH - 1;
            int col = hside ? (wbase + 64 > WI - 1 ? WI - 1 : wbase + 64)
                            : (wbase - 1 < 0 ? 0 : wbase - 1);
            gh_off = (size_t)hr * WI + col;
            sh_off = su_base + (uint32_t)((hrr * RS + 64 + hside) * 4);
        }

        #define LOAD_STAGE(T, ST)                                                   \
        do {                                                                        \
            if (ldu)                                                                \
                cp16(su_off + (uint32_t)((ST) * SU_ST * 4),                         \
                     u + (size_t)(T) * HWs + gu_off);                               \
            if (ldf)                                                                \
                cp16(sf_off + (uint32_t)((ST) * SF_ST * 4),                         \
                     f1 + (size_t)(T) * HWs + gf_off);                              \
            if (ldh)                                                                \
                cp4(sh_off + (uint32_t)((ST) * SU_ST * 4),                          \
                    u + (size_t)(T) * HWs + gh_off);                                \
            CP_COMMIT();                                                            \
        } while (0)

        LOAD_STAGE(0, 0);
        LOAD_STAGE(1, 1);
        LOAD_STAGE(2, 2);

        const float A = 0.34520446044393f;
        const float B = 0.309591078922457f;
        const float C = -2.619182157203629f;
        const float KLAP = 0.01f * 4194304.0f;     // kappa / DX^2

        const float fPW[10] = {
            (float)(PREFD * WQ[0]), (float)(PREFD * WQ[1]), (float)(PREFD * WQ[2]),
            (float)(PREFD * WQ[3]), (float)(PREFD * WQ[4]), (float)(PREFD * WQ[5]),
            (float)(PREFD * WQ[6]), (float)(PREFD * WQ[7]), (float)(PREFD * WQ[8]),
            (float)(PREFD * WQ[9])
        };
        const float fPD[10] = {
            0.0f,
            (float)(PREFD * (WQ[0] - WQ[1])), (float)(PREFD * (WQ[1] - WQ[2])),
            (float)(PREFD * (WQ[2] - WQ[3])), (float)(PREFD * (WQ[3] - WQ[4])),
            (float)(PREFD * (WQ[4] - WQ[5])), (float)(PREFD * (WQ[5] - WQ[6])),
            (float)(PREFD * (WQ[6] - WQ[7])), (float)(PREFD * (WQ[7] - WQ[8])),
            (float)(PREFD * (WQ[8] - WQ[9]))
        };
        const float PREFF = (float)PREFD;

        const float mskw  = (w >= 1 && w <= WI - 2) ? 1.0f : 0.0f;
        const float mskA  = mskw * ((hA     <= HH - 2) ? 1.0f : 0.0f);
        const float mskB  = mskw * ((hA + 1 <= HH - 2) ? 1.0f : 0.0f);

        // Halo column for edge lanes (q at c-1 / c+32 of this warp's span).
        const bool  edge = (lane == 0) || (lane == 31);
        const int   hcol = (lane == 0) ? ((wx == 0) ? 64 : 31)
                                       : ((wx == 1) ? 65 : 32);

        // Tile u rows this warp touches: 2wy .. 2wy+3 (tile row i = h0-1+i).
        const int ur0 = 2 * wy;

        float acc = 0.0f;
        float ucm[11][2];   // [.][0] = row A, [.][1] = row B

        #pragma unroll
        for (int t = 0; t < 11; t++) {
            const int st = t & 3;

            CP_WAIT2();
            __syncthreads();
            if (t + 3 <= 10) { LOAD_STAGE(t + 3, (t + 3) & 3); }
            else             { CP_COMMIT(); }

            const float* ub = su + st * SU_ST + ur0 * RS;     // tile row 2wy
            const float  u0 = ub[c];                          // row hA-1
            const float  u1 = ub[RS + c];                     // row hA (center A)
            const float  u2 = ub[2 * RS + c];                 // row hA+1 (center B)
            const float  u3 = ub[3 * RS + c];                 // row hA+2

            float uh0 = 0.f, uh1 = 0.f, uh2 = 0.f, uh3 = 0.f;
            if (edge) {
                uh0 = ub[hcol];
                uh1 = ub[RS + hcol];
                uh2 = ub[2 * RS + hcol];
                uh3 = ub[3 * RS + hcol];
            }

            const float* fb = sf + st * SF_ST + ur0 * RS;
            const float fA = fb[c];                           // f row hA
            const float fB = fb[RS + c];                      // f row hA+1

            const float caA = u0 + u2;
            const float caB = u1 + u3;
            const float qA  = fmaf(A, caA, B * u1);
            const float qB  = fmaf(A, caB, B * u2);
            const float qEA = fmaf(A, uh0 + uh2, B * uh1);
            const float qEB = fmaf(A, uh1 + uh3, B * uh2);

            float qLA = __shfl_up_sync(0xffffffffu, qA, 1);
            float qRA = __shfl_down_sync(0xffffffffu, qA, 1);
            float qLB = __shfl_up_sync(0xffffffffu, qB, 1);
            float qRB = __shfl_down_sync(0xffffffffu, qB, 1);
            if (lane == 0)  { qLA = qEA; qLB = qEB; }
            if (lane == 31) { qRA = qEA; qRB = qEB; }

            const float cen[2]  = { u1, u2 };
            const float cas[2]  = { caA, caB };
            const float qls[2]  = { qLA, qLB };
            const float qrs[2]  = { qRA, qRB };
            const float ffs[2]  = { fA, fB };
            const float msk[2]  = { mskA, mskB };

            #pragma unroll
            for (int j = 0; j < 2; j++) {
                const float center = cen[j];
                const float conv = qls[j] + qrs[j]
                                 + fmaf(B, cas[j], C * center);
                float fu = center - ffs[j] - KLAP * conv;
                if (t > 0) {
                    float Dv = PREFF * center - fPW[t - 1] * ucm[0][j];
                    #pragma unroll
                    for (int k = 1; k < t; k++)
                        Dv -= fPD[t - k] * ucm[k][j];
                    fu += Dv;
                }
                fu *= msk[j];
                acc = fmaf(fu, fu, acc);
                ucm[t][j] = center;
            }
        }

        block_reduce_add((double)acc, &g_phy, tid);
        #undef LOAD_STAGE
    }

    // ---------------- last-block finalize + reset ----------------
    if (tid == 0) {
        __threadfence();
        unsigned prev = atomicAdd(&g_count, 1u);
        if (prev == NB_TOT - 1) {
            out[0] = (float)(2.0 * g_phy / 46047276.0);   // 11*2046*2046
            out[1] = (float)(g_bc / 41943040.0);          // 10*2048*2048
            g_phy = 0.0;
            g_bc  = 0.0;
            g_count = 0u;
            __threadfence();
        }
    }
}

extern "C" void kernel_launch(void* const* d_in, const int* in_sizes, int n_in,
                              void* d_out, int out_size) {
    const float* u  = (const float*)d_in[0];
    const float* f1 = (const float*)d_in[1];
    float* out = (float*)d_out;

    fused_kernel<<<NB_TOT, 256>>>(u, f1, out);
}